// round 1
// baseline (speedup 1.0000x reference)
#include <cuda_runtime.h>
#include <cuda_bf16.h>
#include <float.h>
#include <stdint.h>

// Problem constants
#define HEADS   12
#define HS      64
#define HID     768
#define BATCH   8
#define SEQ     512
#define M_ROWS  (BATCH*SEQ)        // 4096
#define N_COLS  (HEADS*2*HS)       // 1536

// ---------------- scratch (allocation-free: device globals) ----------------
__device__ __nv_bfloat16 g_xhi[M_ROWS*HID];
__device__ __nv_bfloat16 g_xlo[M_ROWS*HID];
__device__ __nv_bfloat16 g_whi[HID*N_COLS];
__device__ __nv_bfloat16 g_wlo[HID*N_COLS];
__device__ __nv_bfloat16 g_qhi[BATCH*HEADS*SEQ*HS];
__device__ __nv_bfloat16 g_qlo[BATCH*HEADS*SEQ*HS];
__device__ __nv_bfloat16 g_khi[BATCH*HEADS*SEQ*HS];
__device__ __nv_bfloat16 g_klo[BATCH*HEADS*SEQ*HS];
__device__ float g_sin[SEQ*(HS/2)];
__device__ float g_cos[SEQ*(HS/2)];

// ---------------- helpers ----------------
__device__ __forceinline__ uint32_t pack_bf16(__nv_bfloat16 a, __nv_bfloat16 b) {
    __nv_bfloat162 t; t.x = a; t.y = b;
    return *reinterpret_cast<uint32_t*>(&t);
}

__device__ __forceinline__ void split1(float v, __nv_bfloat16& h, __nv_bfloat16& l) {
    h = __float2bfloat16(v);
    l = __float2bfloat16(v - __bfloat162float(h));
}

__device__ __forceinline__ void mma16816(float* c, const uint32_t* a, const uint32_t* b) {
    asm volatile(
        "mma.sync.aligned.m16n8k16.row.col.f32.bf16.bf16.f32 "
        "{%0,%1,%2,%3}, {%4,%5,%6,%7}, {%8,%9}, {%0,%1,%2,%3};\n"
        : "+f"(c[0]), "+f"(c[1]), "+f"(c[2]), "+f"(c[3])
        : "r"(a[0]), "r"(a[1]), "r"(a[2]), "r"(a[3]),
          "r"(b[0]), "r"(b[1]));
}

// ---------------- rope tables: sin/cos[l][j], j in [0,32) ----------------
__global__ void rope_tables_kernel() {
    int i = blockIdx.x * blockDim.x + threadIdx.x;
    if (i >= SEQ * (HS/2)) return;
    int l = i >> 5;
    int j = i & 31;
    // inv_freq = 10000^(-j/32) = exp2(-j * log2(10000)/32)
    float inv = exp2f(-(float)j * (13.287712379549449f / 32.0f));
    float t = (float)l * inv;
    g_sin[i] = sinf(t);
    g_cos[i] = cosf(t);
}

// ---------------- fp32 -> bf16 hi/lo split ----------------
__global__ void split_x_kernel(const float* __restrict__ src) {
    int i = blockIdx.x * blockDim.x + threadIdx.x;
    if (i >= (M_ROWS*HID)/4) return;
    float4 v = reinterpret_cast<const float4*>(src)[i];
    __nv_bfloat16 h0,h1,h2,h3,l0,l1,l2,l3;
    split1(v.x,h0,l0); split1(v.y,h1,l1); split1(v.z,h2,l2); split1(v.w,h3,l3);
    uint2 hv, lv;
    hv.x = pack_bf16(h0,h1); hv.y = pack_bf16(h2,h3);
    lv.x = pack_bf16(l0,l1); lv.y = pack_bf16(l2,l3);
    reinterpret_cast<uint2*>(g_xhi)[i] = hv;
    reinterpret_cast<uint2*>(g_xlo)[i] = lv;
}

__global__ void split_w_kernel(const float* __restrict__ src) {
    int i = blockIdx.x * blockDim.x + threadIdx.x;
    if (i >= (HID*N_COLS)/4) return;
    float4 v = reinterpret_cast<const float4*>(src)[i];
    __nv_bfloat16 h0,h1,h2,h3,l0,l1,l2,l3;
    split1(v.x,h0,l0); split1(v.y,h1,l1); split1(v.z,h2,l2); split1(v.w,h3,l3);
    uint2 hv, lv;
    hv.x = pack_bf16(h0,h1); hv.y = pack_bf16(h2,h3);
    lv.x = pack_bf16(l0,l1); lv.y = pack_bf16(l2,l3);
    reinterpret_cast<uint2*>(g_whi)[i] = hv;
    reinterpret_cast<uint2*>(g_wlo)[i] = lv;
}

// ---------------- GEMM1: Y = X@W + b, fused RoPE, write split q/k ----------
// Block tile 128x128, BK=32, 8 warps in 2(m)x4(n), warp tile 64x32.
__device__ __forceinline__ void rope_store(float v0, float v1, int gm, int gc,
                                           const float* __restrict__ bias) {
    float2 bv = *reinterpret_cast<const float2*>(&bias[gc]);
    v0 += bv.x; v1 += bv.y;
    int h   = gc >> 7;         // head
    int rem = gc & 127;
    int qk  = rem >> 6;        // 0 = q, 1 = k
    int d   = rem & 63;        // even
    int j   = d >> 1;
    int l   = gm & (SEQ-1);
    int bb  = gm >> 9;
    float sn = g_sin[l*32 + j];
    float cs = g_cos[l*32 + j];
    float o0 = v0*cs - v1*sn;
    float o1 = v0*sn + v1*cs;
    __nv_bfloat16 h0,l0,h1,l1;
    split1(o0,h0,l0); split1(o1,h1,l1);
    uint32_t ph = pack_bf16(h0,h1);
    uint32_t pl = pack_bf16(l0,l1);
    int idx = (((bb*HEADS + h)*SEQ + l)*HS + d);
    if (qk == 0) {
        *reinterpret_cast<uint32_t*>(&g_qhi[idx]) = ph;
        *reinterpret_cast<uint32_t*>(&g_qlo[idx]) = pl;
    } else {
        *reinterpret_cast<uint32_t*>(&g_khi[idx]) = ph;
        *reinterpret_cast<uint32_t*>(&g_klo[idx]) = pl;
    }
}

__global__ __launch_bounds__(256) void gemm1_rope_kernel(const float* __restrict__ bias) {
    const int n0 = blockIdx.x * 128;
    const int m0 = blockIdx.y * 128;
    const int tid  = threadIdx.x;
    const int wid  = tid >> 5, lane = tid & 31;
    const int wm = wid >> 2, wn = wid & 3;
    const int gr = lane >> 2, tg = lane & 3;

    __shared__ __nv_bfloat16 sAh[128][34];
    __shared__ __nv_bfloat16 sAl[128][34];
    __shared__ __nv_bfloat16 sBh[128][34];
    __shared__ __nv_bfloat16 sBl[128][34];

    float acc[4][4][4] = {};

    for (int kt = 0; kt < HID; kt += 32) {
        // A tile: 128x32 bf16 (hi & lo), 32-bit chunks
        #pragma unroll
        for (int i = tid; i < 2048; i += 256) {
            int r  = i >> 4;
            int c2 = (i & 15) << 1;
            int go = (m0 + r)*HID + kt + c2;
            *reinterpret_cast<uint32_t*>(&sAh[r][c2]) =
                *reinterpret_cast<const uint32_t*>(&g_xhi[go]);
            *reinterpret_cast<uint32_t*>(&sAl[r][c2]) =
                *reinterpret_cast<const uint32_t*>(&g_xlo[go]);
        }
        // B tile: W[kt..kt+32, n0..n0+128] transposed into [n][k]
        #pragma unroll
        for (int i = tid; i < 4096; i += 256) {
            int c = i >> 7;
            int n = i & 127;
            int go = (kt + c)*N_COLS + n0 + n;
            sBh[n][c] = g_whi[go];
            sBl[n][c] = g_wlo[go];
        }
        __syncthreads();

        #pragma unroll
        for (int kk = 0; kk < 32; kk += 16) {
            uint32_t afh[4][4], afl[4][4], bfh[4][2], bfl[4][2];
            const int c0 = kk + tg*2;
            #pragma unroll
            for (int mi = 0; mi < 4; mi++) {
                int row = wm*64 + mi*16 + gr;
                afh[mi][0] = *reinterpret_cast<const uint32_t*>(&sAh[row  ][c0  ]);
                afh[mi][1] = *reinterpret_cast<const uint32_t*>(&sAh[row+8][c0  ]);
                afh[mi][2] = *reinterpret_cast<const uint32_t*>(&sAh[row  ][c0+8]);
                afh[mi][3] = *reinterpret_cast<const uint32_t*>(&sAh[row+8][c0+8]);
                afl[mi][0] = *reinterpret_cast<const uint32_t*>(&sAl[row  ][c0  ]);
                afl[mi][1] = *reinterpret_cast<const uint32_t*>(&sAl[row+8][c0  ]);
                afl[mi][2] = *reinterpret_cast<const uint32_t*>(&sAl[row  ][c0+8]);
                afl[mi][3] = *reinterpret_cast<const uint32_t*>(&sAl[row+8][c0+8]);
            }
            #pragma unroll
            for (int nj = 0; nj < 4; nj++) {
                int col = wn*32 + nj*8 + gr;
                bfh[nj][0] = *reinterpret_cast<const uint32_t*>(&sBh[col][c0  ]);
                bfh[nj][1] = *reinterpret_cast<const uint32_t*>(&sBh[col][c0+8]);
                bfl[nj][0] = *reinterpret_cast<const uint32_t*>(&sBl[col][c0  ]);
                bfl[nj][1] = *reinterpret_cast<const uint32_t*>(&sBl[col][c0+8]);
            }
            #pragma unroll
            for (int mi = 0; mi < 4; mi++)
                #pragma unroll
                for (int nj = 0; nj < 4; nj++)
                    mma16816(acc[mi][nj], afh[mi], bfh[nj]);
            #pragma unroll
            for (int mi = 0; mi < 4; mi++)
                #pragma unroll
                for (int nj = 0; nj < 4; nj++)
                    mma16816(acc[mi][nj], afh[mi], bfl[nj]);
            #pragma unroll
            for (int mi = 0; mi < 4; mi++)
                #pragma unroll
                for (int nj = 0; nj < 4; nj++)
                    mma16816(acc[mi][nj], afl[mi], bfh[nj]);
        }
        __syncthreads();
    }

    // epilogue: bias + RoPE + split-bf16 store into q/k
    #pragma unroll
    for (int mi = 0; mi < 4; mi++) {
        #pragma unroll
        for (int nj = 0; nj < 4; nj++) {
            int gm0 = m0 + wm*64 + mi*16 + gr;
            int gc  = n0 + wn*32 + nj*8 + tg*2;
            rope_store(acc[mi][nj][0], acc[mi][nj][1], gm0,   gc, bias);
            rope_store(acc[mi][nj][2], acc[mi][nj][3], gm0+8, gc, bias);
        }
    }
}

// ---------------- GEMM2: logits[b,h,m,n] = q.k^T/8 + masking -------------
__global__ __launch_bounds__(256) void gemm2_kernel(const int* __restrict__ amask,
                                                    float* __restrict__ out) {
    const int tn = blockIdx.x, tm = blockIdx.y, bh = blockIdx.z;
    const int tid = threadIdx.x;

    // Fully-below-diagonal tile -> pure -FLT_MAX fill, no compute
    if (tn < tm) {
        const float4 nv = make_float4(-FLT_MAX,-FLT_MAX,-FLT_MAX,-FLT_MAX);
        #pragma unroll 4
        for (int i = tid; i < 128*32; i += 256) {
            int r  = i >> 5;
            int c4 = i & 31;
            *reinterpret_cast<float4*>(
                &out[((size_t)(bh*SEQ + tm*128 + r))*SEQ + tn*128 + c4*4]) = nv;
        }
        return;
    }

    const int bb = bh / HEADS;
    const int wid = tid >> 5, lane = tid & 31;
    const int wm = wid >> 2, wn = wid & 3;
    const int gr = lane >> 2, tg = lane & 3;

    __shared__ __nv_bfloat16 sQh[128][34], sQl[128][34];
    __shared__ __nv_bfloat16 sKh[128][34], sKl[128][34];
    __shared__ int sAmM[128], sAmN[128];

    if (tid < 128)       sAmM[tid]     = amask[bb*SEQ + tm*128 + tid];
    else                 sAmN[tid-128] = amask[bb*SEQ + tn*128 + (tid-128)];

    const __nv_bfloat16* qh = g_qhi + (size_t)bh*SEQ*HS;
    const __nv_bfloat16* ql = g_qlo + (size_t)bh*SEQ*HS;
    const __nv_bfloat16* kh = g_khi + (size_t)bh*SEQ*HS;
    const __nv_bfloat16* kl = g_klo + (size_t)bh*SEQ*HS;

    float acc[4][4][4] = {};

    for (int kt = 0; kt < HS; kt += 32) {
        #pragma unroll
        for (int i = tid; i < 2048; i += 256) {
            int r  = i >> 4;
            int c2 = (i & 15) << 1;
            int gq = (tm*128 + r)*HS + kt + c2;
            int gk = (tn*128 + r)*HS + kt + c2;
            *reinterpret_cast<uint32_t*>(&sQh[r][c2]) =
                *reinterpret_cast<const uint32_t*>(&qh[gq]);
            *reinterpret_cast<uint32_t*>(&sQl[r][c2]) =
                *reinterpret_cast<const uint32_t*>(&ql[gq]);
            *reinterpret_cast<uint32_t*>(&sKh[r][c2]) =
                *reinterpret_cast<const uint32_t*>(&kh[gk]);
            *reinterpret_cast<uint32_t*>(&sKl[r][c2]) =
                *reinterpret_cast<const uint32_t*>(&kl[gk]);
        }
        __syncthreads();

        #pragma unroll
        for (int kk = 0; kk < 32; kk += 16) {
            uint32_t afh[4][4], afl[4][4], bfh[4][2], bfl[4][2];
            const int c0 = kk + tg*2;
            #pragma unroll
            for (int mi = 0; mi < 4; mi++) {
                int row = wm*64 + mi*16 + gr;
                afh[mi][0] = *reinterpret_cast<const uint32_t*>(&sQh[row  ][c0  ]);
                afh[mi][1] = *reinterpret_cast<const uint32_t*>(&sQh[row+8][c0  ]);
                afh[mi][2] = *reinterpret_cast<const uint32_t*>(&sQh[row  ][c0+8]);
                afh[mi][3] = *reinterpret_cast<const uint32_t*>(&sQh[row+8][c0+8]);
                afl[mi][0] = *reinterpret_cast<const uint32_t*>(&sQl[row  ][c0  ]);
                afl[mi][1] = *reinterpret_cast<const uint32_t*>(&sQl[row+8][c0  ]);
                afl[mi][2] = *reinterpret_cast<const uint32_t*>(&sQl[row  ][c0+8]);
                afl[mi][3] = *reinterpret_cast<const uint32_t*>(&sQl[row+8][c0+8]);
            }
            #pragma unroll
            for (int nj = 0; nj < 4; nj++) {
                int col = wn*32 + nj*8 + gr;
                bfh[nj][0] = *reinterpret_cast<const uint32_t*>(&sKh[col][c0  ]);
                bfh[nj][1] = *reinterpret_cast<const uint32_t*>(&sKh[col][c0+8]);
                bfl[nj][0] = *reinterpret_cast<const uint32_t*>(&sKl[col][c0  ]);
                bfl[nj][1] = *reinterpret_cast<const uint32_t*>(&sKl[col][c0+8]);
            }
            #pragma unroll
            for (int mi = 0; mi < 4; mi++)
                #pragma unroll
                for (int nj = 0; nj < 4; nj++)
                    mma16816(acc[mi][nj], afh[mi], bfh[nj]);
            #pragma unroll
            for (int mi = 0; mi < 4; mi++)
                #pragma unroll
                for (int nj = 0; nj < 4; nj++)
                    mma16816(acc[mi][nj], afh[mi], bfl[nj]);
            #pragma unroll
            for (int mi = 0; mi < 4; mi++)
                #pragma unroll
                for (int nj = 0; nj < 4; nj++)
                    mma16816(acc[mi][nj], afl[mi], bfh[nj]);
        }
        __syncthreads();
    }

    // epilogue: scale, mask, store
    #pragma unroll
    for (int mi = 0; mi < 4; mi++) {
        #pragma unroll
        for (int nj = 0; nj < 4; nj++) {
            int lr = wm*64 + mi*16 + gr;
            int ln = wn*32 + nj*8 + tg*2;
            #pragma unroll
            for (int half = 0; half < 2; half++) {
                int lrr = lr + half*8;
                int m = tm*128 + lrr;
                int n = tn*128 + ln;
                float s0 = acc[mi][nj][half*2 + 0] * 0.125f;
                float s1 = acc[mi][nj][half*2 + 1] * 0.125f;
                bool vm  = (sAmM[lrr] != 0);
                float w0 = (n   >= m && vm && sAmN[ln]   != 0) ? s0 : -FLT_MAX;
                float w1 = (n+1 >= m && vm && sAmN[ln+1] != 0) ? s1 : -FLT_MAX;
                float2 st; st.x = w0; st.y = w1;
                *reinterpret_cast<float2*>(&out[((size_t)(bh*SEQ + m))*SEQ + n]) = st;
            }
        }
    }
}

// ---------------- launch ----------------
extern "C" void kernel_launch(void* const* d_in, const int* in_sizes, int n_in,
                              void* d_out, int out_size) {
    const float* X    = (const float*)d_in[0];   // (8,512,768)
    const float* W    = (const float*)d_in[1];   // (768,1536)
    const float* bias = (const float*)d_in[2];   // (1536,)
    const int*   am   = (const int*)d_in[3];     // (8,512) int32
    float* out = (float*)d_out;                  // (8,12,512,512)

    rope_tables_kernel<<<(SEQ*(HS/2) + 255)/256, 256>>>();
    split_x_kernel<<<((M_ROWS*HID)/4 + 255)/256, 256>>>(X);
    split_w_kernel<<<((HID*N_COLS)/4 + 255)/256, 256>>>(W);
    gemm1_rope_kernel<<<dim3(N_COLS/128, M_ROWS/128), 256>>>(bias);
    gemm2_kernel<<<dim3(4, 4, BATCH*HEADS), 256>>>(am, out);
}

// round 6
// speedup vs baseline: 1.4326x; 1.4326x over previous
#include <cuda_runtime.h>
#include <cuda_bf16.h>
#include <float.h>
#include <stdint.h>

// Problem constants
#define HEADS   12
#define HS      64
#define HID     768
#define BATCH   8
#define SEQ     512
#define M_ROWS  (BATCH*SEQ)        // 4096
#define N_COLS  (HEADS*2*HS)       // 1536

// ---------------- scratch (allocation-free: device globals) ----------------
__device__ __nv_bfloat16 g_xhi[M_ROWS*HID];
__device__ __nv_bfloat16 g_xlo[M_ROWS*HID];
__device__ __nv_bfloat16 g_bhiT[N_COLS*HID];   // W^T split-hi: [n][k] K-major
__device__ __nv_bfloat16 g_bloT[N_COLS*HID];   // W^T split-lo
__device__ __nv_bfloat16 g_qhi[BATCH*HEADS*SEQ*HS];
__device__ __nv_bfloat16 g_qlo[BATCH*HEADS*SEQ*HS];
__device__ __nv_bfloat16 g_khi[BATCH*HEADS*SEQ*HS];  // pre-scaled by 0.125
__device__ __nv_bfloat16 g_klo[BATCH*HEADS*SEQ*HS];
__device__ float g_sin[SEQ*(HS/2)];
__device__ float g_cos[SEQ*(HS/2)];

// ---------------- helpers ----------------
__device__ __forceinline__ uint32_t pack_bf16(__nv_bfloat16 a, __nv_bfloat16 b) {
    __nv_bfloat162 t; t.x = a; t.y = b;
    return *reinterpret_cast<uint32_t*>(&t);
}
__device__ __forceinline__ void split1(float v, __nv_bfloat16& h, __nv_bfloat16& l) {
    h = __float2bfloat16(v);
    l = __float2bfloat16(v - __bfloat162float(h));
}
__device__ __forceinline__ uint32_t smem_u32(const void* p) {
    uint32_t a;
    asm("{ .reg .u64 t; cvta.to.shared.u64 t, %1; cvt.u32.u64 %0, t; }" : "=r"(a) : "l"(p));
    return a;
}
__device__ __forceinline__ void cpasync16(uint32_t dst, const void* src) {
    asm volatile("cp.async.cg.shared.global [%0], [%1], 16;\n" :: "r"(dst), "l"(src));
}
__device__ __forceinline__ void ldsm_x4(uint32_t* r, uint32_t addr) {
    asm volatile("ldmatrix.sync.aligned.m8n8.x4.shared.b16 {%0,%1,%2,%3}, [%4];"
        : "=r"(r[0]), "=r"(r[1]), "=r"(r[2]), "=r"(r[3]) : "r"(addr));
}
__device__ __forceinline__ void mma16816(float* c, const uint32_t* a, const uint32_t* b) {
    asm volatile(
        "mma.sync.aligned.m16n8k16.row.col.f32.bf16.bf16.f32 "
        "{%0,%1,%2,%3}, {%4,%5,%6,%7}, {%8,%9}, {%0,%1,%2,%3};\n"
        : "+f"(c[0]), "+f"(c[1]), "+f"(c[2]), "+f"(c[3])
        : "r"(a[0]), "r"(a[1]), "r"(a[2]), "r"(a[3]),
          "r"(b[0]), "r"(b[1]));
}

// Padded tile: 128 rows x 32 bf16 cols, row stride 40 bf16 (80B) -> LDSM & cp.async
// bank-conflict-free (8-row groups cover all 32 banks exactly once).
#define TPAD    40
#define TILE_B  10240u    // 128*40*2

// ---------------- rope tables ----------------
__global__ void rope_tables_kernel() {
    int i = blockIdx.x * blockDim.x + threadIdx.x;
    if (i >= SEQ * (HS/2)) return;
    int l = i >> 5;
    int j = i & 31;
    float inv = exp2f(-(float)j * (13.287712379549449f / 32.0f));
    float t = (float)l * inv;
    g_sin[i] = sinf(t);
    g_cos[i] = cosf(t);
}

// ---------------- X -> bf16 hi/lo split ----------------
__global__ void split_x_kernel(const float* __restrict__ src) {
    int i = blockIdx.x * blockDim.x + threadIdx.x;
    if (i >= (M_ROWS*HID)/4) return;
    float4 v = reinterpret_cast<const float4*>(src)[i];
    __nv_bfloat16 h0,h1,h2,h3,l0,l1,l2,l3;
    split1(v.x,h0,l0); split1(v.y,h1,l1); split1(v.z,h2,l2); split1(v.w,h3,l3);
    uint2 hv, lv;
    hv.x = pack_bf16(h0,h1); hv.y = pack_bf16(h2,h3);
    lv.x = pack_bf16(l0,l1); lv.y = pack_bf16(l2,l3);
    reinterpret_cast<uint2*>(g_xhi)[i] = hv;
    reinterpret_cast<uint2*>(g_xlo)[i] = lv;
}

// ---------------- W -> transposed split: [n][k] ----------------
__global__ void split_wT_kernel(const float* __restrict__ W) {
    __shared__ float tile[32][33];
    int n0 = blockIdx.x * 32, k0 = blockIdx.y * 32;
    int tx = threadIdx.x, ty = threadIdx.y;   // 32 x 8
    #pragma unroll
    for (int i = 0; i < 4; i++) {
        int k = k0 + ty + i*8;
        tile[ty + i*8][tx] = W[k*N_COLS + n0 + tx];
    }
    __syncthreads();
    #pragma unroll
    for (int i = 0; i < 4; i++) {
        int n = n0 + ty + i*8;
        float v = tile[tx][ty + i*8];
        __nv_bfloat16 h, l; split1(v, h, l);
        g_bhiT[n*HID + k0 + tx] = h;
        g_bloT[n*HID + k0 + tx] = l;
    }
}

// ---------------- GEMM1 epilogue: bias + RoPE + split store ----------------
__device__ __forceinline__ void rope_store(float v0, float v1, int gm, int gc,
                                           const float* __restrict__ bias) {
    float2 bv = *reinterpret_cast<const float2*>(&bias[gc]);
    v0 += bv.x; v1 += bv.y;
    int h   = gc >> 7;
    int rem = gc & 127;
    int qk  = rem >> 6;
    int d   = rem & 63;
    int j   = d >> 1;
    int l   = gm & (SEQ-1);
    int bb  = gm >> 9;
    float sn = g_sin[l*32 + j];
    float cs = g_cos[l*32 + j];
    float o0 = v0*cs - v1*sn;
    float o1 = v0*sn + v1*cs;
    int idx = (((bb*HEADS + h)*SEQ + l)*HS + d);
    if (qk == 0) {
        __nv_bfloat16 h0,l0,h1,l1;
        split1(o0,h0,l0); split1(o1,h1,l1);
        *reinterpret_cast<uint32_t*>(&g_qhi[idx]) = pack_bf16(h0,h1);
        *reinterpret_cast<uint32_t*>(&g_qlo[idx]) = pack_bf16(l0,l1);
    } else {
        // fold 1/sqrt(HS)=0.125 into k (exact: power of 2)
        __nv_bfloat16 h0,l0,h1,l1;
        split1(o0*0.125f,h0,l0); split1(o1*0.125f,h1,l1);
        *reinterpret_cast<uint32_t*>(&g_khi[idx]) = pack_bf16(h0,h1);
        *reinterpret_cast<uint32_t*>(&g_klo[idx]) = pack_bf16(l0,l1);
    }
}

// ---------------- GEMM1: mma.sync, ldmatrix, cp.async 2-stage -------------
// CTA 128x128, BK=32, 24 stages. 8 warps 2(m)x4(n), warp tile 64x32.
// smem/stage: Ah | Al | Bh | Bl each TILE_B. 2 stages = 81920 B dynamic.
#define G1_STAGE_B (4u*TILE_B)
#define G1_SMEM    (2u*G1_STAGE_B)
#define G1_STAGES  (HID/32)

__device__ __forceinline__ void g1_load_stage(int s, int tid, int m0, int n0, uint32_t sbase) {
    const uint32_t sb = sbase + (uint32_t)(s & 1) * G1_STAGE_B;
    const int kt = s * 32;
    #pragma unroll
    for (int c = tid; c < 512; c += 256) {       // A: 128 rows x 4 chunks(16B)
        int r = c >> 2, ck = c & 3;
        uint32_t so = (uint32_t)(r*TPAD*2 + ck*16);
        int go = (m0 + r)*HID + kt + ck*8;
        cpasync16(sb + so,              &g_xhi[go]);
        cpasync16(sb + TILE_B + so,     &g_xlo[go]);
    }
    #pragma unroll
    for (int c = tid; c < 512; c += 256) {       // B: 128 n-rows x 4 chunks
        int n = c >> 2, ck = c & 3;
        uint32_t so = (uint32_t)(n*TPAD*2 + ck*16);
        int go = (n0 + n)*HID + kt + ck*8;
        cpasync16(sb + 2u*TILE_B + so,  &g_bhiT[go]);
        cpasync16(sb + 3u*TILE_B + so,  &g_bloT[go]);
    }
    asm volatile("cp.async.commit_group;\n" ::: "memory");
}

__global__ __launch_bounds__(256) void gemm1_kernel(const float* __restrict__ bias) {
    extern __shared__ __align__(128) char smem[];
    const uint32_t sbase = smem_u32(smem);
    const int tid = threadIdx.x, wid = tid >> 5, lane = tid & 31;
    const int wm = wid >> 2, wn = wid & 3;
    const int gr = lane >> 2, tg = lane & 3;
    const int n0 = blockIdx.x * 128, m0 = blockIdx.y * 128;

    // ldmatrix lane-geometry (offsets in elements; ks adds 16 to col)
    const int a_row = wm*64 + (lane & 15);            // + mi*16
    const int a_col = (lane >> 4) * 8;                // + ks*16
    const int b_row = wn*32 + (lane & 7) + ((lane >> 4) * 8);  // + nj2*16
    const int b_col = ((lane >> 3) & 1) * 8;          // + ks*16

    float acc[4][4][4] = {};

    g1_load_stage(0, tid, m0, n0, sbase);
    g1_load_stage(1, tid, m0, n0, sbase);

    for (int s = 0; s < G1_STAGES; s++) {
        if (s < G1_STAGES - 1) asm volatile("cp.async.wait_group 1;\n" ::: "memory");
        else                   asm volatile("cp.async.wait_group 0;\n" ::: "memory");
        __syncthreads();
        const uint32_t sb = sbase + (uint32_t)(s & 1) * G1_STAGE_B;

        #pragma unroll
        for (int ks = 0; ks < 2; ks++) {
            uint32_t afh[4][4], afl[4][4], bfh[4][2], bfl[4][2];
            const int ac = a_col + ks*16;
            const int bc = b_col + ks*16;
            #pragma unroll
            for (int mi = 0; mi < 4; mi++) {
                uint32_t off = (uint32_t)(((a_row + mi*16)*TPAD + ac) * 2);
                ldsm_x4(afh[mi], sb + off);
                ldsm_x4(afl[mi], sb + TILE_B + off);
            }
            #pragma unroll
            for (int nj2 = 0; nj2 < 2; nj2++) {
                uint32_t off = (uint32_t)(((b_row + nj2*16)*TPAD + bc) * 2);
                uint32_t th[4], tl[4];
                ldsm_x4(th, sb + 2u*TILE_B + off);
                ldsm_x4(tl, sb + 3u*TILE_B + off);
                bfh[nj2*2  ][0] = th[0]; bfh[nj2*2  ][1] = th[1];
                bfh[nj2*2+1][0] = th[2]; bfh[nj2*2+1][1] = th[3];
                bfl[nj2*2  ][0] = tl[0]; bfl[nj2*2  ][1] = tl[1];
                bfl[nj2*2+1][0] = tl[2]; bfl[nj2*2+1][1] = tl[3];
            }
            if (ks == 1 && s + 2 < G1_STAGES) {
                __syncthreads();                      // all LDSM of stage s done
                g1_load_stage(s + 2, tid, m0, n0, sbase);
            }
            #pragma unroll
            for (int mi = 0; mi < 4; mi++)
                #pragma unroll
                for (int nj = 0; nj < 4; nj++)
                    mma16816(acc[mi][nj], afh[mi], bfh[nj]);
            #pragma unroll
            for (int mi = 0; mi < 4; mi++)
                #pragma unroll
                for (int nj = 0; nj < 4; nj++)
                    mma16816(acc[mi][nj], afh[mi], bfl[nj]);
            #pragma unroll
            for (int mi = 0; mi < 4; mi++)
                #pragma unroll
                for (int nj = 0; nj < 4; nj++)
                    mma16816(acc[mi][nj], afl[mi], bfh[nj]);
        }
    }

    // epilogue: bias + RoPE + split store
    #pragma unroll
    for (int mi = 0; mi < 4; mi++) {
        #pragma unroll
        for (int nj = 0; nj < 4; nj++) {
            int gm0 = m0 + wm*64 + mi*16 + gr;
            int gc  = n0 + wn*32 + nj*8 + tg*2;
            rope_store(acc[mi][nj][0], acc[mi][nj][1], gm0,   gc, bias);
            rope_store(acc[mi][nj][2], acc[mi][nj][3], gm0+8, gc, bias);
        }
    }
}

// ---------------- GEMM2: q.k^T (k pre-scaled) + masking --------------------
// CTA 128x128 over (tn,tm,bh). K=64 loaded once: 8 tiles (Qh,Ql,Kh,Kl x 2 kt).
#define G2_SMEM (8u*TILE_B)

__global__ __launch_bounds__(256) void gemm2_kernel(const int* __restrict__ amask,
                                                    float* __restrict__ out) {
    const int tn = blockIdx.x, tm = blockIdx.y, bh = blockIdx.z;
    const int tid = threadIdx.x;

    if (tn < tm) {   // fully-below-diagonal tile -> pure fill
        const float4 nv = make_float4(-FLT_MAX,-FLT_MAX,-FLT_MAX,-FLT_MAX);
        #pragma unroll 4
        for (int i = tid; i < 128*32; i += 256) {
            int r  = i >> 5;
            int c4 = i & 31;
            *reinterpret_cast<float4*>(
                &out[((size_t)(bh*SEQ + tm*128 + r))*SEQ + tn*128 + c4*4]) = nv;
        }
        return;
    }

    extern __shared__ __align__(128) char smem[];
    const uint32_t sbase = smem_u32(smem);
    const int bb = bh / HEADS;
    const int wid = tid >> 5, lane = tid & 31;
    const int wm = wid >> 2, wn = wid & 3;
    const int gr = lane >> 2, tg = lane & 3;

    __shared__ int sAmM[128], sAmN[128];
    if (tid < 128)       sAmM[tid]     = amask[bb*SEQ + tm*128 + tid];
    else                 sAmN[tid-128] = amask[bb*SEQ + tn*128 + (tid-128)];

    const __nv_bfloat16* qh = g_qhi + (size_t)bh*SEQ*HS;
    const __nv_bfloat16* ql = g_qlo + (size_t)bh*SEQ*HS;
    const __nv_bfloat16* kh = g_khi + (size_t)bh*SEQ*HS;
    const __nv_bfloat16* kl = g_klo + (size_t)bh*SEQ*HS;

    // load all 8 tiles: tile index = kt*4 + {0:Qh,1:Ql,2:Kh,3:Kl}
    #pragma unroll
    for (int kt = 0; kt < 2; kt++) {
        #pragma unroll
        for (int c = tid; c < 512; c += 256) {
            int r = c >> 2, ck = c & 3;
            uint32_t so = (uint32_t)(r*TPAD*2 + ck*16);
            int gq = (tm*128 + r)*HS + kt*32 + ck*8;
            int gk = (tn*128 + r)*HS + kt*32 + ck*8;
            uint32_t tb = sbase + (uint32_t)(kt*4) * TILE_B;
            cpasync16(tb              + so, &qh[gq]);
            cpasync16(tb + TILE_B     + so, &ql[gq]);
            cpasync16(tb + 2u*TILE_B  + so, &kh[gk]);
            cpasync16(tb + 3u*TILE_B  + so, &kl[gk]);
        }
    }
    asm volatile("cp.async.commit_group;\n" ::: "memory");
    asm volatile("cp.async.wait_group 0;\n" ::: "memory");
    __syncthreads();

    const int a_row = wm*64 + (lane & 15);
    const int a_col = (lane >> 4) * 8;
    const int b_row = wn*32 + (lane & 7) + ((lane >> 4) * 8);
    const int b_col = ((lane >> 3) & 1) * 8;

    float acc[4][4][4] = {};

    #pragma unroll
    for (int kt = 0; kt < 2; kt++) {
        const uint32_t tb = sbase + (uint32_t)(kt*4) * TILE_B;
        #pragma unroll
        for (int ks = 0; ks < 2; ks++) {
            uint32_t afh[4][4], afl[4][4], bfh[4][2], bfl[4][2];
            const int ac = a_col + ks*16;
            const int bc = b_col + ks*16;
            #pragma unroll
            for (int mi = 0; mi < 4; mi++) {
                uint32_t off = (uint32_t)(((a_row + mi*16)*TPAD + ac) * 2);
                ldsm_x4(afh[mi], tb + off);
                ldsm_x4(afl[mi], tb + TILE_B + off);
            }
            #pragma unroll
            for (int nj2 = 0; nj2 < 2; nj2++) {
                uint32_t off = (uint32_t)(((b_row + nj2*16)*TPAD + bc) * 2);
                uint32_t th[4], tl[4];
                ldsm_x4(th, tb + 2u*TILE_B + off);
                ldsm_x4(tl, tb + 3u*TILE_B + off);
                bfh[nj2*2  ][0] = th[0]; bfh[nj2*2  ][1] = th[1];
                bfh[nj2*2+1][0] = th[2]; bfh[nj2*2+1][1] = th[3];
                bfl[nj2*2  ][0] = tl[0]; bfl[nj2*2  ][1] = tl[1];
                bfl[nj2*2+1][0] = tl[2]; bfl[nj2*2+1][1] = tl[3];
            }
            #pragma unroll
            for (int mi = 0; mi < 4; mi++)
                #pragma unroll
                for (int nj = 0; nj < 4; nj++)
                    mma16816(acc[mi][nj], afh[mi], bfh[nj]);
            #pragma unroll
            for (int mi = 0; mi < 4; mi++)
                #pragma unroll
                for (int nj = 0; nj < 4; nj++)
                    mma16816(acc[mi][nj], afh[mi], bfl[nj]);
            #pragma unroll
            for (int mi = 0; mi < 4; mi++)
                #pragma unroll
                for (int nj = 0; nj < 4; nj++)
                    mma16816(acc[mi][nj], afl[mi], bfh[nj]);
        }
    }

    // epilogue: mask + store (scale already folded into k)
    #pragma unroll
    for (int mi = 0; mi < 4; mi++) {
        #pragma unroll
        for (int nj = 0; nj < 4; nj++) {
            int lr = wm*64 + mi*16 + gr;
            int ln = wn*32 + nj*8 + tg*2;
            #pragma unroll
            for (int half = 0; half < 2; half++) {
                int lrr = lr + half*8;
                int m = tm*128 + lrr;
                int n = tn*128 + ln;
                float s0 = acc[mi][nj][half*2 + 0];
                float s1 = acc[mi][nj][half*2 + 1];
                bool vm  = (sAmM[lrr] != 0);
                float w0 = (n   >= m && vm && sAmN[ln]   != 0) ? s0 : -FLT_MAX;
                float w1 = (n+1 >= m && vm && sAmN[ln+1] != 0) ? s1 : -FLT_MAX;
                float2 st; st.x = w0; st.y = w1;
                *reinterpret_cast<float2*>(&out[((size_t)(bh*SEQ + m))*SEQ + n]) = st;
            }
        }
    }
}

// ---------------- launch ----------------
extern "C" void kernel_launch(void* const* d_in, const int* in_sizes, int n_in,
                              void* d_out, int out_size) {
    const float* X    = (const float*)d_in[0];   // (8,512,768)
    const float* W    = (const float*)d_in[1];   // (768,1536)
    const float* bias = (const float*)d_in[2];   // (1536,)
    const int*   am   = (const int*)d_in[3];     // (8,512) int32
    float* out = (float*)d_out;                  // (8,12,512,512)

    cudaFuncSetAttribute(gemm1_kernel, cudaFuncAttributeMaxDynamicSharedMemorySize, G1_SMEM);
    cudaFuncSetAttribute(gemm2_kernel, cudaFuncAttributeMaxDynamicSharedMemorySize, G2_SMEM);

    rope_tables_kernel<<<(SEQ*(HS/2) + 255)/256, 256>>>();
    split_x_kernel<<<((M_ROWS*HID)/4 + 255)/256, 256>>>(X);
    split_wT_kernel<<<dim3(N_COLS/32, HID/32), dim3(32, 8)>>>(W);
    gemm1_kernel<<<dim3(N_COLS/128, M_ROWS/128), 256, G1_SMEM>>>(bias);
    gemm2_kernel<<<dim3(4, 4, BATCH*HEADS), 256, G2_SMEM>>>(am, out);
}